// round 15
// baseline (speedup 1.0000x reference)
#include <cuda_runtime.h>

#define ALPHA 100.0f
#define MG 5

static constexpr int B = 32, C = 3, H = 512, W = 512;
static constexpr int HW = H * W;
static constexpr int GROUPS = B * H * (W / 4);   // 2,097,152 float4 groups
static constexpr float INV_N = 1.0f / (float(B) * C * H * W);

__global__ void zero_out_kernel(float* out) { out[0] = 0.0f; }

__device__ __forceinline__ float pix_w(int p, int xmin, int xmax, int ty, bool cond)
{
    const int tx = min(p - xmin + 6, xmax + 5 - p);   // >=6 inside, 1..5 ramp, <=0 outside
    if (cond) {
        const int fmin = min(min(tx, ty), 5);
        return (fmin > 0) ? (float)fmin * (ALPHA / (float)MG) : 1.0f;
    }
    return (tx >= 6 && ty >= 6) ? ALPHA : 1.0f;
}

__global__ void __launch_bounds__(256, 8)
mae_bbox_kernel(const float* __restrict__ x,
                const float* __restrict__ y,
                const int*   __restrict__ bbox,
                float*       __restrict__ out)
{
    float a0 = 0.f, a1 = 0.f, a2 = 0.f, a3 = 0.f;

    for (int g = blockIdx.x * blockDim.x + threadIdx.x; g < GROUPS;
         g += gridDim.x * blockDim.x)
    {
        const int b   = g >> 16;            // / (512*128)
        const int rem = g & 65535;
        const int h   = rem >> 7;           // row
        const int x0  = (rem & 127) << 2;   // first of 4 pixels

        const int base = b * C * HW + h * W + x0;

        // issue all 6 streaming loads first — maximal front-batched MLP
        float4 xv[C], yv[C];
        #pragma unroll
        for (int c = 0; c < C; c++) {
            xv[c] = __ldcs(reinterpret_cast<const float4*>(x + base + c * HW));
            yv[c] = __ldcs(reinterpret_cast<const float4*>(y + base + c * HW));
        }

        // bbox[b]: uniform-per-warp broadcast loads, L1-resident
        const int* bb = bbox + b * 8;
        const int xmin = min(min(bb[0], bb[2]), min(bb[4], bb[6]));
        const int xmax = max(max(bb[0], bb[2]), max(bb[4], bb[6]));
        const int ymin = min(min(bb[1], bb[3]), min(bb[5], bb[7]));
        const int ymax = max(max(bb[1], bb[3]), max(bb[5], bb[7]));
        const bool cond = (xmin - MG > 0) && (xmax + MG < W) &&
                          (ymin - MG > 0) && (ymax + MG < H);

        const int ty = min(h - ymin + 6, ymax + 5 - h);

        const float w0 = pix_w(x0 + 0, xmin, xmax, ty, cond);
        const float w1 = pix_w(x0 + 1, xmin, xmax, ty, cond);
        const float w2 = pix_w(x0 + 2, xmin, xmax, ty, cond);
        const float w3 = pix_w(x0 + 3, xmin, xmax, ty, cond);

        #pragma unroll
        for (int c = 0; c < C; c++) {
            a0 += fabsf(xv[c].x - yv[c].x) * w0;
            a1 += fabsf(xv[c].y - yv[c].y) * w1;
            a2 += fabsf(xv[c].z - yv[c].z) * w2;
            a3 += fabsf(xv[c].w - yv[c].w) * w3;
        }
    }

    float acc = (a0 + a1) + (a2 + a3);

    // warp reduce
    #pragma unroll
    for (int o = 16; o > 0; o >>= 1)
        acc += __shfl_down_sync(0xffffffff, acc, o);

    __shared__ float sm[8];
    const int lane = threadIdx.x & 31;
    const int wid  = threadIdx.x >> 5;
    if (lane == 0) sm[wid] = acc;
    __syncthreads();

    if (wid == 0) {
        acc = (lane < 8) ? sm[lane] : 0.0f;
        #pragma unroll
        for (int o = 4; o > 0; o >>= 1)
            acc += __shfl_down_sync(0xffffffff, acc, o);
        if (lane == 0)
            atomicAdd(out, acc * INV_N);
    }
}

extern "C" void kernel_launch(void* const* d_in, const int* in_sizes, int n_in,
                              void* d_out, int out_size)
{
    const float* x    = (const float*)d_in[0];
    const float* y    = (const float*)d_in[1];
    const int*   bbox = (const int*)d_in[2];
    float* out = (float*)d_out;

    zero_out_kernel<<<1, 1>>>(out);
    mae_bbox_kernel<<<1184, 256>>>(x, y, bbox, out);
}

// round 16
// speedup vs baseline: 1.0192x; 1.0192x over previous
#include <cuda_runtime.h>

#define ALPHA 100.0f
#define MG 5

static constexpr int B = 32, C = 3, H = 512, W = 512;
static constexpr int HW = H * W;
static constexpr int GROUPS = B * H * (W / 4);   // 2,097,152 float4 groups
static constexpr float INV_N = 1.0f / (float(B) * C * H * W);

__global__ void zero_out_kernel(float* out) { out[0] = 0.0f; }

__device__ __forceinline__ float pix_w(int p, int xmin, int xmax, int ty, bool cond)
{
    const int tx = min(p - xmin + 6, xmax + 5 - p);   // >=6 inside, 1..5 ramp, <=0 outside
    if (cond) {
        const int fmin = min(min(tx, ty), 5);
        return (fmin > 0) ? (float)fmin * (ALPHA / (float)MG) : 1.0f;
    }
    return (tx >= 6 && ty >= 6) ? ALPHA : 1.0f;
}

__global__ void __launch_bounds__(256, 8)
mae_bbox_kernel(const float* __restrict__ x,
                const float* __restrict__ y,
                const int*   __restrict__ bbox,
                float*       __restrict__ out)
{
    float a0 = 0.f, a1 = 0.f, a2 = 0.f, a3 = 0.f;

    for (int g = blockIdx.x * blockDim.x + threadIdx.x; g < GROUPS;
         g += gridDim.x * blockDim.x)
    {
        const int b   = g >> 16;            // / (512*128)
        const int rem = g & 65535;
        const int h   = rem >> 7;           // row
        const int x0  = (rem & 127) << 2;   // first of 4 pixels

        const int base = b * C * HW + h * W + x0;

        // issue all 6 streaming loads first — maximal front-batched MLP
        float4 xv[C], yv[C];
        #pragma unroll
        for (int c = 0; c < C; c++) {
            xv[c] = __ldcs(reinterpret_cast<const float4*>(x + base + c * HW));
            yv[c] = __ldcs(reinterpret_cast<const float4*>(y + base + c * HW));
        }

        // bbox[b]: uniform-per-warp broadcast loads, L1-resident
        const int* bb = bbox + b * 8;
        const int xmin = min(min(bb[0], bb[2]), min(bb[4], bb[6]));
        const int xmax = max(max(bb[0], bb[2]), max(bb[4], bb[6]));
        const int ymin = min(min(bb[1], bb[3]), min(bb[5], bb[7]));
        const int ymax = max(max(bb[1], bb[3]), max(bb[5], bb[7]));
        const bool cond = (xmin - MG > 0) && (xmax + MG < W) &&
                          (ymin - MG > 0) && (ymax + MG < H);

        const int ty = min(h - ymin + 6, ymax + 5 - h);

        const float w0 = pix_w(x0 + 0, xmin, xmax, ty, cond);
        const float w1 = pix_w(x0 + 1, xmin, xmax, ty, cond);
        const float w2 = pix_w(x0 + 2, xmin, xmax, ty, cond);
        const float w3 = pix_w(x0 + 3, xmin, xmax, ty, cond);

        #pragma unroll
        for (int c = 0; c < C; c++) {
            a0 += fabsf(xv[c].x - yv[c].x) * w0;
            a1 += fabsf(xv[c].y - yv[c].y) * w1;
            a2 += fabsf(xv[c].z - yv[c].z) * w2;
            a3 += fabsf(xv[c].w - yv[c].w) * w3;
        }
    }

    float acc = (a0 + a1) + (a2 + a3);

    // warp reduce
    #pragma unroll
    for (int o = 16; o > 0; o >>= 1)
        acc += __shfl_down_sync(0xffffffff, acc, o);

    __shared__ float sm[8];
    const int lane = threadIdx.x & 31;
    const int wid  = threadIdx.x >> 5;
    if (lane == 0) sm[wid] = acc;
    __syncthreads();

    if (wid == 0) {
        acc = (lane < 8) ? sm[lane] : 0.0f;
        #pragma unroll
        for (int o = 4; o > 0; o >>= 1)
            acc += __shfl_down_sync(0xffffffff, acc, o);
        if (lane == 0)
            atomicAdd(out, acc * INV_N);
    }
}

extern "C" void kernel_launch(void* const* d_in, const int* in_sizes, int n_in,
                              void* d_out, int out_size)
{
    const float* x    = (const float*)d_in[0];
    const float* y    = (const float*)d_in[1];
    const int*   bbox = (const int*)d_in[2];
    float* out = (float*)d_out;

    zero_out_kernel<<<1, 1>>>(out);
    mae_bbox_kernel<<<1184, 256>>>(x, y, bbox, out);
}

// round 17
// speedup vs baseline: 1.0692x; 1.0490x over previous
#include <cuda_runtime.h>

#define ALPHA 100.0f
#define MG 5

static constexpr int B = 32, C = 3, H = 512, W = 512;
static constexpr int HW = H * W;
static constexpr int GROUPS = B * H * (W / 4);   // 2,097,152 float4 groups
static constexpr float INV_N = 1.0f / (float(B) * C * H * W);

__device__ __forceinline__ float pix_w(int p, int xmin, int xmax, int ty, bool cond)
{
    const int tx = min(p - xmin + 6, xmax + 5 - p);   // >=6 inside, 1..5 ramp, <=0 outside
    if (cond) {
        const int fmin = min(min(tx, ty), 5);
        return (fmin > 0) ? (float)fmin * (ALPHA / (float)MG) : 1.0f;
    }
    return (tx >= 6 && ty >= 6) ? ALPHA : 1.0f;
}

__global__ void __launch_bounds__(256, 8)
mae_bbox_kernel(const float* __restrict__ x,
                const float* __restrict__ y,
                const int*   __restrict__ bbox,
                float*       __restrict__ out)
{
    // Block 0 zeroes the (poisoned) output at kernel start. Safe: every block's
    // atomicAdd is preceded by its entire ~1770-iteration DRAM-bound mainloop
    // (>=1e5 cycles), while this store retires within ~1e2 cycles of launch of
    // the single co-resident wave. The fence publishes the zero GPU-wide long
    // before any consumer atomic can issue.
    if (blockIdx.x == 0 && threadIdx.x == 0) {
        out[0] = 0.0f;
        __threadfence();
    }

    float a0 = 0.f, a1 = 0.f, a2 = 0.f, a3 = 0.f;

    for (int g = blockIdx.x * blockDim.x + threadIdx.x; g < GROUPS;
         g += gridDim.x * blockDim.x)
    {
        const int b   = g >> 16;            // / (512*128)
        const int rem = g & 65535;
        const int h   = rem >> 7;           // row
        const int x0  = (rem & 127) << 2;   // first of 4 pixels

        const int base = b * C * HW + h * W + x0;

        // issue all 6 streaming loads first — maximal front-batched MLP
        float4 xv[C], yv[C];
        #pragma unroll
        for (int c = 0; c < C; c++) {
            xv[c] = __ldcs(reinterpret_cast<const float4*>(x + base + c * HW));
            yv[c] = __ldcs(reinterpret_cast<const float4*>(y + base + c * HW));
        }

        // bbox[b]: uniform-per-warp broadcast loads, L1-resident
        const int* bb = bbox + b * 8;
        const int xmin = min(min(bb[0], bb[2]), min(bb[4], bb[6]));
        const int xmax = max(max(bb[0], bb[2]), max(bb[4], bb[6]));
        const int ymin = min(min(bb[1], bb[3]), min(bb[5], bb[7]));
        const int ymax = max(max(bb[1], bb[3]), max(bb[5], bb[7]));
        const bool cond = (xmin - MG > 0) && (xmax + MG < W) &&
                          (ymin - MG > 0) && (ymax + MG < H);

        const int ty = min(h - ymin + 6, ymax + 5 - h);

        const float w0 = pix_w(x0 + 0, xmin, xmax, ty, cond);
        const float w1 = pix_w(x0 + 1, xmin, xmax, ty, cond);
        const float w2 = pix_w(x0 + 2, xmin, xmax, ty, cond);
        const float w3 = pix_w(x0 + 3, xmin, xmax, ty, cond);

        #pragma unroll
        for (int c = 0; c < C; c++) {
            a0 += fabsf(xv[c].x - yv[c].x) * w0;
            a1 += fabsf(xv[c].y - yv[c].y) * w1;
            a2 += fabsf(xv[c].z - yv[c].z) * w2;
            a3 += fabsf(xv[c].w - yv[c].w) * w3;
        }
    }

    float acc = (a0 + a1) + (a2 + a3);

    // warp reduce
    #pragma unroll
    for (int o = 16; o > 0; o >>= 1)
        acc += __shfl_down_sync(0xffffffff, acc, o);

    __shared__ float sm[8];
    const int lane = threadIdx.x & 31;
    const int wid  = threadIdx.x >> 5;
    if (lane == 0) sm[wid] = acc;
    __syncthreads();

    if (wid == 0) {
        acc = (lane < 8) ? sm[lane] : 0.0f;
        #pragma unroll
        for (int o = 4; o > 0; o >>= 1)
            acc += __shfl_down_sync(0xffffffff, acc, o);
        if (lane == 0)
            atomicAdd(out, acc * INV_N);
    }
}

extern "C" void kernel_launch(void* const* d_in, const int* in_sizes, int n_in,
                              void* d_out, int out_size)
{
    const float* x    = (const float*)d_in[0];
    const float* y    = (const float*)d_in[1];
    const int*   bbox = (const int*)d_in[2];
    float* out = (float*)d_out;

    mae_bbox_kernel<<<1184, 256>>>(x, y, bbox, out);
}